// round 2
// baseline (speedup 1.0000x reference)
#include <cuda_runtime.h>

// ============================================================================
// 2-layer tanh RNN, B=32, L=2048, H=512, persistent layer-pipelined kernel.
//
// 128 persistent CTAs (all resident: 1 CTA/SM, 128 <= 148 SMs):
//   CTA 0..63   : layer 0, output columns [cta*8, cta*8+8)
//   CTA 64..127 : layer 1, output columns [(cta-64)*8, ...)
// Each CTA keeps its weight slices (W_i[:,cols], W_h[:,cols]) in SMEM for the
// whole run (weight-stationary). Per step it computes
//   h[b][c] = tanh( sum_k in[b][k]*Wi[k][c] + hprev[b][k]*Wh[k][c] + bias[c] )
// for all 32 batch rows and its 8 columns.
//
// Cross-CTA dataflow:
//   layer-0 h lives in a 4-slot ring buffer in global memory (g_ring)
//   layer-1 h lives directly in d_out ([B,L,H]) — output doubles as state
// Sync: per-step completion counters (g_cntA/g_cntB) + volatile polling.
// Ring slot t%4 is only overwritten after cntB[t-4] (layer-1 consumed it).
//
// Compute: fp32 packed FMA (fma.rn.f32x2) — 2 fp32 FMAs per instruction.
// K=512 is split across the 32 lanes of each warp (lane ln handles
// k = ln, ln+32, ..., ln+480); partial sums are reduced with an SMEM
// transpose (conflict-free: 33-float row pad).
// ============================================================================

#define BB 32
#define LL 2048
#define HH 512
#define NCOLS 8
#define GA 64
#define GB 64
#define NTHR 256
#define WROW 12   // padded SMEM weight row: 8 cols + 4 pad (conflict-free LDS.128)

__device__ float g_ring[4 * BB * HH];   // layer-0 h ring, 256 KB
__device__ int   g_cntA[LL];
__device__ int   g_cntB[LL];

__device__ __forceinline__ int ldvol(const int* p) {
    return *((volatile const int*)p);
}

#define FMA2(d, a, w) asm volatile("fma.rn.f32x2 %0, %1, %2, %0;" \
                                   : "+l"(d) : "l"(a), "l"(w))

__global__ void zero_flags_kernel() {
    int i = blockIdx.x * blockDim.x + threadIdx.x;
    if (i < LL) { g_cntA[i] = 0; g_cntB[i] = 0; }
}

__global__ __launch_bounds__(NTHR) void rnn_kernel(
    const float* __restrict__ x,   const float* __restrict__ h0in,
    const float* __restrict__ Wi,  const float* __restrict__ bi,
    const float* __restrict__ Wh,  const float* __restrict__ bh,
    float* __restrict__ out, int write_final)
{
    extern __shared__ float smem[];
    float* Ws0 = smem;                 // [512][WROW] input-side weight slice
    float* Ws1 = smem + HH * WROW;     // [512][WROW] hidden-side weight slice
    float* red = smem + 2 * HH * WROW; // [8 warps][32][33] reduction scratch

    const int  cta   = blockIdx.x;
    const bool isA   = (cta < GA);
    const int  layer = isA ? 0 : 1;
    const int  c0    = (isA ? cta : cta - GA) * NCOLS;
    const int  tid   = threadIdx.x;
    const int  w     = tid >> 5;
    const int  ln    = tid & 31;

    // ---- stage weight slices into SMEM (once) ----
    {
        const float* wi_g = Wi + (size_t)layer * HH * HH;
        const float* wh_g = Wh + (size_t)layer * HH * HH;
        for (int i = tid; i < HH * NCOLS; i += NTHR) {
            int k = i >> 3, c = i & 7;
            Ws0[k * WROW + c] = wi_g[k * HH + c0 + c];
            Ws1[k * WROW + c] = wh_g[k * HH + c0 + c];
        }
    }
    __syncthreads();

    // this thread's final output element: batch myb, column myc
    const int   myb  = w * 4 + (ln >> 3);
    const int   myc  = c0 + (ln & 7);
    const float bias = bi[layer * HH + myc] + bh[layer * HH + myc];
    const int   b0   = w * 4;   // this warp's 4 batch rows
    float* redw = red + w * (32 * 33);

    // per-lane SMEM weight base: lane ln owns k = ln + 32*j
    const float* wrow0 = Ws0 + ln * WROW;
    const float* wrow1 = Ws1 + ln * WROW;

    #pragma unroll 1
    for (int t = 0; t < LL; t++) {
        // ---------------- sync / flow control ----------------
        if (tid == 0) {
            if (isA) {
                if (t >= 1) while (ldvol(&g_cntA[t - 1]) < GA) __nanosleep(40);
                if (t >= 4) while (ldvol(&g_cntB[t - 4]) < GB) __nanosleep(40);
            } else {
                while (ldvol(&g_cntA[t]) < GA) __nanosleep(40);
                if (t >= 1) while (ldvol(&g_cntB[t - 1]) < GB) __nanosleep(40);
            }
        }
        __syncthreads();

        // ---------------- input pointers for this step ----------------
        const float* px; long long sx;   // "input" matrix (x for L0, h0[t] for L1)
        const float* ph; long long sh;   // "hidden" matrix (h_prev of this layer)
        if (isA) {
            px = x + (long long)t * HH;  sx = (long long)LL * HH;
            if (t == 0) { ph = h0in;                                sh = HH; }
            else        { ph = g_ring + ((t - 1) & 3) * (BB * HH);  sh = HH; }
        } else {
            px = g_ring + (t & 3) * (BB * HH);  sx = HH;
            if (t == 0) { ph = h0in + BB * HH;              sh = HH; }
            else        { ph = out + (long long)(t - 1) * HH; sh = (long long)LL * HH; }
        }

        const float* pxb[4]; const float* phb[4];
        #pragma unroll
        for (int bb = 0; bb < 4; bb++) {
            pxb[bb] = px + (long long)(b0 + bb) * sx + ln;
            phb[bb] = ph + (long long)(b0 + bb) * sh + ln;
        }

        // ---------------- main FMA loop ----------------
        // acc[bb*4+cp] packs columns (2cp, 2cp+1) for batch row b0+bb
        unsigned long long acc[16];
        #pragma unroll
        for (int i = 0; i < 16; i++) acc[i] = 0ull;

        #pragma unroll
        for (int j = 0; j < 16; j++) {
            // weights for k = ln + 32*j : 8 cols of Wi, 8 cols of Wh
            ulonglong2 wiA = *reinterpret_cast<const ulonglong2*>(wrow0 + j * 32 * WROW);
            ulonglong2 wiB = *reinterpret_cast<const ulonglong2*>(wrow0 + j * 32 * WROW + 4);
            ulonglong2 whA = *reinterpret_cast<const ulonglong2*>(wrow1 + j * 32 * WROW);
            ulonglong2 whB = *reinterpret_cast<const ulonglong2*>(wrow1 + j * 32 * WROW + 4);
            #pragma unroll
            for (int bb = 0; bb < 4; bb++) {
                float xv = __ldcg(pxb[bb] + 32 * j);
                float hv = __ldcg(phb[bb] + 32 * j);
                unsigned long long xp, hp;
                asm("mov.b64 %0, {%1,%1};" : "=l"(xp) : "f"(xv));
                asm("mov.b64 %0, {%1,%1};" : "=l"(hp) : "f"(hv));
                FMA2(acc[bb * 4 + 0], xp, wiA.x);
                FMA2(acc[bb * 4 + 1], xp, wiA.y);
                FMA2(acc[bb * 4 + 2], xp, wiB.x);
                FMA2(acc[bb * 4 + 3], xp, wiB.y);
                FMA2(acc[bb * 4 + 0], hp, whA.x);
                FMA2(acc[bb * 4 + 1], hp, whA.y);
                FMA2(acc[bb * 4 + 2], hp, whB.x);
                FMA2(acc[bb * 4 + 3], hp, whB.y);
            }
        }

        // ---------------- reduce over the 32-lane K split ----------------
        #pragma unroll
        for (int i = 0; i < 16; i++) {
            float2 v = *reinterpret_cast<float2*>(&acc[i]);
            int a = (i >> 2) * 8 + (i & 3) * 2;   // bb*8 + cp*2
            redw[ln * 33 + a]     = v.x;
            redw[ln * 33 + a + 1] = v.y;
        }
        __syncwarp();
        float sum = 0.f;
        #pragma unroll
        for (int a = 0; a < 32; a++) sum += redw[a * 33 + ln];

        float hval = tanhf(sum + bias);

        // ---------------- publish ----------------
        if (isA) {
            g_ring[(t & 3) * (BB * HH) + myb * HH + myc] = hval;
            if (write_final && t == LL - 1)
                out[(long long)BB * LL * HH + myb * HH + myc] = hval;
        } else {
            out[(long long)myb * LL * HH + (long long)t * HH + myc] = hval;
            if (write_final && t == LL - 1)
                out[(long long)BB * LL * HH + BB * HH + myb * HH + myc] = hval;
        }
        __threadfence();
        __syncthreads();
        if (tid == 0) atomicAdd(isA ? &g_cntA[t] : &g_cntB[t], 1);
    }
}

extern "C" void kernel_launch(void* const* d_in, const int* in_sizes, int n_in,
                              void* d_out, int out_size)
{
    const float* x  = (const float*)d_in[0];
    const float* h0 = (const float*)d_in[1];
    const float* Wi = (const float*)d_in[2];
    const float* bi = (const float*)d_in[3];
    const float* Wh = (const float*)d_in[4];
    const float* bh = (const float*)d_in[5];
    float* out = (float*)d_out;

    int write_final = (out_size >= BB * LL * HH + 2 * BB * HH) ? 1 : 0;

    size_t smem = (size_t)(2 * HH * WROW + 8 * 32 * 33) * sizeof(float); // ~83 KB
    cudaFuncSetAttribute(rnn_kernel,
                         cudaFuncAttributeMaxDynamicSharedMemorySize, (int)smem);

    zero_flags_kernel<<<(LL + 255) / 256, 256>>>();
    rnn_kernel<<<GA + GB, NTHR, smem>>>(x, h0, Wi, bi, Wh, bh, out, write_final);
}

// round 3
// speedup vs baseline: 1.6191x; 1.6191x over previous
#include <cuda_runtime.h>

// ============================================================================
// 2-layer tanh RNN, B=32, L=2048, H=512 — persistent layer-pipelined kernel v2.
//
// 128 persistent CTAs (1/SM):
//   CTA 0..63   : layer 0, output columns [cta*8, cta*8+8)
//   CTA 64..127 : layer 1, columns [(cta-64)*8, ...)
// Weight slices live in SMEM for the whole run (lane-interleaved float4,
// conflict-free LDS.128). K=512 split: lane ln owns k in [16*ln, 16*ln+16),
// inputs read as float4 (coalesced LDG.128). Partial sums reduced via padded
// SMEM transpose.
//
// Sync v2 (no threadfence, no atomic round-trip):
//   producers: STG (relaxed) -> __syncthreads -> tid0: red.release.gpu.add
//   consumers: every thread polls ld.acquire.gpu on the step counter
// Ungated work is computed before polling (x-side for L0, own-hidden side
// for L1) so poll latency is hidden behind FMAs.
//
// Dataflow: layer-0 h -> 4-slot global ring; layer-1 h -> d_out directly.
// Cross-SM reads use __ldcg (L2 coherence point; ring slots recur in L1).
// ============================================================================

#define BB 32
#define LL 2048
#define HH 512
#define GA 64
#define GB 64
#define NTHR 256

__device__ float g_ring[4 * BB * HH];   // layer-0 h ring, 256 KB
__device__ int   g_cntA[LL];
__device__ int   g_cntB[LL];

__device__ __forceinline__ void wait_ge(const int* p, int val) {
    int v;
    while (true) {
        asm volatile("ld.acquire.gpu.b32 %0, [%1];" : "=r"(v) : "l"(p) : "memory");
        if (v >= val) return;
        __nanosleep(20);
    }
}
__device__ __forceinline__ void rel_add(int* p) {
    asm volatile("red.release.gpu.add.u32 [%0], %1;" :: "l"(p), "r"(1u) : "memory");
}

#define FMA2(d, a, w) asm volatile("fma.rn.f32x2 %0, %1, %2, %0;" \
                                   : "+l"(d) : "l"(a), "l"(w))

__device__ __forceinline__ unsigned long long pack2(float v) {
    unsigned long long r;
    asm("mov.b64 %0, {%1,%1};" : "=l"(r) : "f"(v));
    return r;
}

__global__ void zero_flags_kernel() {
    int i = blockIdx.x * blockDim.x + threadIdx.x;
    if (i < LL) { g_cntA[i] = 0; g_cntB[i] = 0; }
}

// Accumulate one side (one weight matrix pair) into acc[16].
// acc[b*4 + q] packs output columns (2q, 2q+1) for batch row b0+b.
// Weights: lane-interleaved ulonglong2 arrays wA (cols 0-3), wB (cols 4-7),
// index [i*32 + ln] holds k = 16*ln + i.
__device__ __forceinline__ void accum_side(
    unsigned long long acc[16],
    const ulonglong2* __restrict__ wA, const ulonglong2* __restrict__ wB,
    const float* __restrict__ p, long long stride, int b0, int ln, bool useL2)
{
    #pragma unroll
    for (int i4 = 0; i4 < 4; i4++) {
        float4 v[4];
        #pragma unroll
        for (int b = 0; b < 4; b++) {
            const float4* addr = (const float4*)(p + (long long)(b0 + b) * stride
                                                 + 16 * ln + 4 * i4);
            v[b] = useL2 ? __ldcg(addr) : *addr;
        }
        #pragma unroll
        for (int e = 0; e < 4; e++) {
            int i = 4 * i4 + e;
            ulonglong2 a  = wA[i * 32 + ln];
            ulonglong2 bq = wB[i * 32 + ln];
            #pragma unroll
            for (int b = 0; b < 4; b++) {
                float xv = (e == 0) ? v[b].x : (e == 1) ? v[b].y
                         : (e == 2) ? v[b].z : v[b].w;
                unsigned long long xp = pack2(xv);
                FMA2(acc[b * 4 + 0], xp, a.x);
                FMA2(acc[b * 4 + 1], xp, a.y);
                FMA2(acc[b * 4 + 2], xp, bq.x);
                FMA2(acc[b * 4 + 3], xp, bq.y);
            }
        }
    }
}

__global__ __launch_bounds__(NTHR) void rnn_kernel(
    const float* __restrict__ x,   const float* __restrict__ h0in,
    const float* __restrict__ Wi,  const float* __restrict__ bi,
    const float* __restrict__ Wh,  const float* __restrict__ bh,
    float* __restrict__ out, int write_final)
{
    extern __shared__ float smem[];
    float4* sWiA = (float4*)smem;          // [512] cols 0-3 of Wi slice
    float4* sWiB = sWiA + HH;              // [512] cols 4-7
    float4* sWhA = sWiB + HH;
    float4* sWhB = sWhA + HH;
    float*  red  = (float*)(sWhB + HH);    // [8 warps][32][33]

    const int  cta   = blockIdx.x;
    const bool isA   = (cta < GA);
    const int  layer = isA ? 0 : 1;
    const int  c0    = (isA ? cta : cta - GA) * 8;
    const int  tid   = threadIdx.x;
    const int  w     = tid >> 5;
    const int  ln    = tid & 31;

    // ---- stage weight slices (once), lane-interleaved layout ----
    {
        const float* wi_g = Wi + (size_t)layer * HH * HH + c0;
        const float* wh_g = Wh + (size_t)layer * HH * HH + c0;
        for (int k = tid; k < HH; k += NTHR) {
            int idx = (k & 15) * 32 + (k >> 4);   // [i][owner_lane]
            const float4* ri = (const float4*)(wi_g + (size_t)k * HH);
            const float4* rh = (const float4*)(wh_g + (size_t)k * HH);
            sWiA[idx] = ri[0];  sWiB[idx] = ri[1];
            sWhA[idx] = rh[0];  sWhB[idx] = rh[1];
        }
    }
    __syncthreads();

    const int   myb  = w * 4 + (ln >> 3);
    const int   myc  = c0 + (ln & 7);
    const float bias = bi[layer * HH + myc] + bh[layer * HH + myc];
    const int   b0   = w * 4;
    float* redw = red + w * (32 * 33);

    const ulonglong2* wiA = (const ulonglong2*)sWiA;
    const ulonglong2* wiB = (const ulonglong2*)sWiB;
    const ulonglong2* whA = (const ulonglong2*)sWhA;
    const ulonglong2* whB = (const ulonglong2*)sWhB;

    #pragma unroll 1
    for (int t = 0; t < LL; t++) {
        unsigned long long acc[16];
        #pragma unroll
        for (int i = 0; i < 16; i++) acc[i] = 0ull;

        if (isA) {
            // x-side first: no gating, hides the poll below.
            accum_side(acc, wiA, wiB, x + (long long)t * HH,
                       (long long)LL * HH, b0, ln, false);
            const float* ph; long long sh;
            if (t == 0) { ph = h0in; sh = HH; }
            else {
                wait_ge(&g_cntA[t - 1], GA);
                ph = g_ring + ((t - 1) & 3) * (BB * HH); sh = HH;
            }
            accum_side(acc, whA, whB, ph, sh, b0, ln, true);
        } else {
            // own-hidden side first (own group's t-1: almost always ready).
            const float* ph; long long sh;
            if (t == 0) { ph = h0in + BB * HH; sh = HH; }
            else {
                wait_ge(&g_cntB[t - 1], GB);
                ph = out + (long long)(t - 1) * HH; sh = (long long)LL * HH;
            }
            accum_side(acc, whA, whB, ph, sh, b0, ln, true);
            wait_ge(&g_cntA[t], GA);
            accum_side(acc, wiA, wiB, g_ring + (t & 3) * (BB * HH),
                       HH, b0, ln, true);
        }

        // ---- reduce over 32-lane K split (padded SMEM transpose) ----
        #pragma unroll
        for (int i = 0; i < 16; i++) {
            float2 v = *reinterpret_cast<float2*>(&acc[i]);
            int a = (i >> 2) * 8 + (i & 3) * 2;
            redw[ln * 33 + a]     = v.x;
            redw[ln * 33 + a + 1] = v.y;
        }
        __syncwarp();
        float s0 = 0.f, s1 = 0.f, s2 = 0.f, s3 = 0.f;
        #pragma unroll
        for (int a = 0; a < 32; a += 4) {
            s0 += redw[(a + 0) * 33 + ln];
            s1 += redw[(a + 1) * 33 + ln];
            s2 += redw[(a + 2) * 33 + ln];
            s3 += redw[(a + 3) * 33 + ln];
        }
        float hval = tanhf((s0 + s1) + (s2 + s3) + bias);
        __syncwarp();   // redw safe to rewrite next step (warp-private region)

        // ---- publish ----
        if (isA) {
            if (t >= 4) wait_ge(&g_cntB[t - 4], GB);  // ring slot reuse safety
            g_ring[(t & 3) * (BB * HH) + myb * HH + myc] = hval;
            if (write_final && t == LL - 1)
                out[(long long)BB * LL * HH + myb * HH + myc] = hval;
        } else {
            out[(long long)myb * LL * HH + (long long)t * HH + myc] = hval;
            if (write_final && t == LL - 1)
                out[(long long)BB * LL * HH + BB * HH + myb * HH + myc] = hval;
        }
        __syncthreads();                       // all STGs issued CTA-wide
        if (tid == 0) rel_add(isA ? &g_cntA[t] : &g_cntB[t]);  // cumulative release
    }
}

extern "C" void kernel_launch(void* const* d_in, const int* in_sizes, int n_in,
                              void* d_out, int out_size)
{
    const float* x  = (const float*)d_in[0];
    const float* h0 = (const float*)d_in[1];
    const float* Wi = (const float*)d_in[2];
    const float* bi = (const float*)d_in[3];
    const float* Wh = (const float*)d_in[4];
    const float* bh = (const float*)d_in[5];
    float* out = (float*)d_out;

    int write_final = (out_size >= BB * LL * HH + 2 * BB * HH) ? 1 : 0;

    size_t smem = (size_t)(4 * HH * 4 + 8 * 32 * 33) * sizeof(float); // ~66 KB
    cudaFuncSetAttribute(rnn_kernel,
                         cudaFuncAttributeMaxDynamicSharedMemorySize, (int)smem);

    zero_flags_kernel<<<(LL + 255) / 256, 256>>>();
    rnn_kernel<<<GA + GB, NTHR, smem>>>(x, h0, Wi, bi, Wh, bh, out, write_final);
}